// round 11
// baseline (speedup 1.0000x reference)
#include <cuda_runtime.h>
#include <cuda_bf16.h>
#include <cstdint>
#include <math.h>

#define Bb 4
#define Ii 32
#define Nn 4096
#define Dd 64
#define WP 0.5f

#define STR 68                  // padded SMEM row stride (floats)
#define NTILE 32                // 128-row tiles per batch
#define TPB (NTILE * (NTILE + 1) / 2)   // 528 tile-pairs per batch

// ---------------- device scratch ----------------
__device__ int      g_dtype;
__device__ int      g_inst[Bb * Nn];
__device__ int      g_cnt[Bb * Ii];
__device__ float    g_lp[Bb * Ii];
__device__ float    g_ln[Bb * Ii];
__device__ int      g_ofs[Bb * (Ii + 1)];
__device__ int      g_cur[Bb * (Ii + 1)];
__device__ int      g_pos[Bb * Nn];
__device__ int      g_insts[Bb * Nn];
__device__ int      g_lo[Bb * Nn];
__device__ int      g_hi[Bb * Nn];
__device__ float    g_xtf[Bb * Nn * Dd];
__device__ float    g_te[Bb * Nn];
__device__ float    g_se[Bb * Nn];
__device__ float    g_ps[Bb * Nn];

__device__ __forceinline__ float to_tf32(float v) {
    float r;
    asm("cvt.rna.tf32.f32 %0, %1;" : "=f"(r) : "f"(v));
    return r;
}
__device__ __forceinline__ void mma8(float* d, const uint32_t* a, uint32_t b0, uint32_t b1) {
    asm volatile(
        "mma.sync.aligned.m16n8k8.row.col.f32.tf32.tf32.f32 "
        "{%0,%1,%2,%3}, {%4,%5,%6,%7}, {%8,%9}, {%0,%1,%2,%3};"
        : "+f"(d[0]), "+f"(d[1]), "+f"(d[2]), "+f"(d[3])
        : "r"(a[0]), "r"(a[1]), "r"(a[2]), "r"(a[3]), "r"(b0), "r"(b1));
}

// ---------------- kernel 1: detect label dtype + zero small scratch ----------------
__global__ void detect_kernel(const unsigned int* lab_words) {
    __shared__ int notInt, notFloat;
    int t = threadIdx.x;
    if (t == 0) { notInt = 0; notFloat = 0; }
    __syncthreads();
    int vi = 0, vf = 0;
    for (int i = t; i < 4096; i += blockDim.x) {
        unsigned int w = lab_words[i];
        if (w > 1u) vi = 1;
        if (w != 0u && w != 0x3F800000u) vf = 1;
    }
    if (vi) atomicOr(&notInt, 1);
    if (vf) atomicOr(&notFloat, 1);
    __syncthreads();
    if (t == 0) g_dtype = (!notInt) ? 1 : ((!notFloat) ? 2 : 0);
    if (t < Bb * Ii) { g_cnt[t] = 0; g_lp[t] = 0.f; g_ln[t] = 0.f; }
}

// ---------------- kernel 2: instance ids + counts ----------------
__global__ void inst_kernel(const void* lab) {
    int idx = blockIdx.x * blockDim.x + threadIdx.x;
    if (idx >= Bb * Nn) return;
    int b = idx / Nn;
    int n = idx - b * Nn;
    int dt = g_dtype;
    const unsigned char* l8  = (const unsigned char*)lab;
    const int*           l32 = (const int*)lab;
    const float*         lf  = (const float*)lab;
    int inst = -1;
    #pragma unroll 1
    for (int i = 0; i < Ii; i++) {
        size_t base = ((size_t)b * Ii + i) * Nn + n;
        bool v;
        if (dt == 0)      v = (l8[base] != 0);
        else if (dt == 1) v = (l32[base] != 0);
        else              v = (lf[base] != 0.0f);
        if (v) { inst = i; break; }
    }
    g_inst[idx] = inst;
    if (inst >= 0) atomicAdd(&g_cnt[b * Ii + inst], 1);
}

// ---------------- kernel 2b: per-batch prefix sums ----------------
__global__ void ofs_kernel() {
    int b = threadIdx.x;
    if (b >= Bb) return;
    int acc = 0;
    for (int i = 0; i < Ii; i++) {
        g_ofs[b * (Ii + 1) + i] = acc;
        g_cur[b * (Ii + 1) + i] = acc;
        acc += g_cnt[b * Ii + i];
    }
    g_ofs[b * (Ii + 1) + Ii] = acc;
    g_cur[b * (Ii + 1) + Ii] = acc;
}

// ---------------- kernel 2c: sorted positions (warp-aggregated atomics) ----------------
__global__ void pos_kernel() {
    int idx = blockIdx.x * blockDim.x + threadIdx.x;
    if (idx >= Bb * Nn) return;
    int b = idx >> 12;
    int lane = threadIdx.x & 31;
    int i = g_inst[idx];
    int slot = (i >= 0) ? i : Ii;
    int key = b * (Ii + 1) + slot;
    unsigned peers = __match_any_sync(0xffffffffu, key);
    int leader = __ffs(peers) - 1;
    int rank = __popc(peers & ((1u << lane) - 1u));
    int base = 0;
    if (lane == leader) base = atomicAdd(&g_cur[key], __popc(peers));
    base = __shfl_sync(0xffffffffu, base, leader);
    int pos = base + rank;
    g_pos[idx] = pos;
    int sp = b * Nn + pos;
    g_insts[sp] = i;
    g_lo[sp] = (i >= 0) ? g_ofs[b * (Ii + 1) + i] : 0;
    g_hi[sp] = (i >= 0) ? g_ofs[b * (Ii + 1) + i + 1] : 0;
}

// ---------------- kernel 2d: scatter x (tf32) + zero stats ----------------
__global__ void copy_kernel(const float* __restrict__ x) {
    int t = blockIdx.x * blockDim.x + threadIdx.x;
    int point = t >> 4;
    int chunk = t & 15;
    int b = point >> 12;
    int pos = g_pos[point];
    float4 v = *(const float4*)(x + (size_t)point * Dd + chunk * 4);
    v.x = to_tf32(v.x); v.y = to_tf32(v.y); v.z = to_tf32(v.z); v.w = to_tf32(v.w);
    *(float4*)(g_xtf + ((size_t)b * Nn + pos) * Dd + chunk * 4) = v;
    if (t < Bb * Nn) { g_te[t] = 0.f; g_se[t] = 0.f; g_ps[t] = 0.f; }
}

// ---------------- kernel 3: symmetric tile-pair tf32 mma sim ----------------
// grid: Bb * 528 blocks, 256 threads. Block: tile pair (rt, ct), ct >= rt,
// computes 128x128 products once; off-diag tiles emit row AND column sums.
__global__ __launch_bounds__(256, 2) void sim_kernel() {
    extern __shared__ float sm[];
    float* As    = sm;                    // [128*STR]
    float* Bsm   = sm + 128 * STR;        // [128*STR]
    float* colte = sm + 2 * 128 * STR;    // [128]
    float* colse = colte + 128;           // [128]
    float* colps = colte + 256;           // [128]

    int tid = threadIdx.x;
    int wid = tid >> 5;
    int lid = tid & 31;
    int g   = lid >> 2;
    int tg  = lid & 3;

    // decode (b, rt, ct)
    int id = blockIdx.x;
    int b  = id / TPB;
    int t  = id - b * TPB;
    int rt = 0;
    while (t >= NTILE - rt) { t -= NTILE - rt; rt++; }
    int ct = rt + t;
    bool diag = (ct == rt);
    int p0 = rt * 128;
    int c0 = ct * 128;
    const float* xb = g_xtf + (size_t)b * Nn * Dd;

    int ldr = tid >> 4;      // 0..15
    int cg  = tid & 15;

    // stage A and B bands (128 rows x 64 dims each)
    #pragma unroll
    for (int i = 0; i < 8; i++) {
        int row = ldr + i * 16;
        float4 va = *(const float4*)(xb + (size_t)(p0 + row) * Dd + cg * 4);
        *(float4*)(&As[row * STR + cg * 4]) = va;
        float4 vb = *(const float4*)(xb + (size_t)(c0 + row) * Dd + cg * 4);
        *(float4*)(&Bsm[row * STR + cg * 4]) = vb;
    }
    if (tid < 128) { colte[tid] = 0.f; colse[tid] = 0.f; colps[tid] = 0.f; }
    __syncthreads();

    // A fragments: warp wid owns rows wid*16+g, +8
    uint32_t af[8][4];
    {
        int rc = wid * 16 + g;
        #pragma unroll
        for (int kk = 0; kk < 8; kk++) {
            af[kk][0] = __float_as_uint(As[rc * STR + kk * 8 + tg]);
            af[kk][1] = __float_as_uint(As[(rc + 8) * STR + kk * 8 + tg]);
            af[kk][2] = __float_as_uint(As[rc * STR + kk * 8 + tg + 4]);
            af[kk][3] = __float_as_uint(As[(rc + 8) * STR + kk * 8 + tg + 4]);
        }
    }

    int r0g = p0 + wid * 16 + g;
    int lo0 = g_lo[b * Nn + r0g],     hi0 = g_hi[b * Nn + r0g];
    int lo1 = g_lo[b * Nn + r0g + 8], hi1 = g_hi[b * Nn + r0g + 8];
    unsigned wLo = __reduce_min_sync(0xffffffffu, (unsigned)min(lo0, lo1));
    unsigned wHi = __reduce_max_sync(0xffffffffu, (unsigned)max(hi0, hi1));
    unsigned rng0 = (unsigned)(hi0 - lo0), rng1 = (unsigned)(hi1 - lo1);

    float te0 = 0.f, te1 = 0.f, se0 = 0.f, se1 = 0.f, ps0 = 0.f, ps1 = 0.f;

    #pragma unroll
    for (int u = 0; u < 2; u++) {
        float acc[8][4];
        #pragma unroll
        for (int nt = 0; nt < 8; nt++)
            #pragma unroll
            for (int j = 0; j < 4; j++) acc[nt][j] = 0.f;

        #pragma unroll
        for (int kk = 0; kk < 8; kk++) {
            #pragma unroll
            for (int nt = 0; nt < 8; nt++) {
                int nb = u * 64 + nt * 8 + g;
                uint32_t b0 = __float_as_uint(Bsm[nb * STR + kk * 8 + tg]);
                uint32_t b1 = __float_as_uint(Bsm[nb * STR + kk * 8 + tg + 4]);
                mma8(acc[nt], af[kk], b0, b1);
            }
        }

        int uStart = c0 + u * 64;
        bool ovl = (wLo < (unsigned)(uStart + 64)) && (wHi > (unsigned)uStart);

        #pragma unroll
        for (int nt = 0; nt < 8; nt++) {
            int gc0 = uStart + nt * 8 + 2 * tg;
            float s00 = acc[nt][0], s01 = acc[nt][1];
            float s10 = acc[nt][2], s11 = acc[nt][3];
            float e00 = __expf(s00), e01 = __expf(s01);
            float e10 = __expf(s10), e11 = __expf(s11);
            te0 += e00 + e01;
            te1 += e10 + e11;

            float m00 = 0.f, m01 = 0.f, m10 = 0.f, m11 = 0.f;
            float q00 = 0.f, q01 = 0.f, q10 = 0.f, q11 = 0.f;
            if (ovl) {
                unsigned d00 = (unsigned)(gc0 - lo0), d01 = d00 + 1;
                unsigned d10 = (unsigned)(gc0 - lo1), d11 = d10 + 1;
                if (d00 < rng0) { m00 = e00; float d = s00 - 1.f; q00 = d * d; }
                if (d01 < rng0) { m01 = e01; float d = s01 - 1.f; q01 = d * d; }
                if (d10 < rng1) { m10 = e10; float d = s10 - 1.f; q10 = d * d; }
                if (d11 < rng1) { m11 = e11; float d = s11 - 1.f; q11 = d * d; }
                se0 += m00 + m01; ps0 += q00 + q01;
                se1 += m10 + m11; ps1 += q10 + q11;
            }

            if (!diag) {
                // column sums over this warp's 16 rows (butterfly over g-lanes)
                float v0 = e00 + e10;
                float v1 = e01 + e11;
                #pragma unroll
                for (int off = 16; off >= 4; off >>= 1) {
                    v0 += __shfl_xor_sync(0xffffffffu, v0, off);
                    v1 += __shfl_xor_sync(0xffffffffu, v1, off);
                }
                int lc = nt * 8 + 2 * tg + u * 64;
                if (g == 0) {
                    atomicAdd(&colte[lc], v0);
                    atomicAdd(&colte[lc + 1], v1);
                }
                if (ovl) {
                    float w0 = m00 + m10, w1 = m01 + m11;
                    float y0 = q00 + q10, y1 = q01 + q11;
                    #pragma unroll
                    for (int off = 16; off >= 4; off >>= 1) {
                        w0 += __shfl_xor_sync(0xffffffffu, w0, off);
                        w1 += __shfl_xor_sync(0xffffffffu, w1, off);
                        y0 += __shfl_xor_sync(0xffffffffu, y0, off);
                        y1 += __shfl_xor_sync(0xffffffffu, y1, off);
                    }
                    if (g == 0) {
                        if (w0 != 0.f) atomicAdd(&colse[lc], w0);
                        if (w1 != 0.f) atomicAdd(&colse[lc + 1], w1);
                        if (y0 != 0.f) atomicAdd(&colps[lc], y0);
                        if (y1 != 0.f) atomicAdd(&colps[lc + 1], y1);
                    }
                }
            }
        }
    }

    // row partials -> global
    #pragma unroll
    for (int off = 2; off > 0; off >>= 1) {
        te0 += __shfl_down_sync(0xffffffffu, te0, off, 4);
        te1 += __shfl_down_sync(0xffffffffu, te1, off, 4);
        se0 += __shfl_down_sync(0xffffffffu, se0, off, 4);
        se1 += __shfl_down_sync(0xffffffffu, se1, off, 4);
        ps0 += __shfl_down_sync(0xffffffffu, ps0, off, 4);
        ps1 += __shfl_down_sync(0xffffffffu, ps1, off, 4);
    }
    if (tg == 0) {
        size_t o0 = (size_t)b * Nn + r0g;
        atomicAdd(&g_te[o0], te0);
        atomicAdd(&g_se[o0], se0);
        atomicAdd(&g_ps[o0], ps0);
        atomicAdd(&g_te[o0 + 8], te1);
        atomicAdd(&g_se[o0 + 8], se1);
        atomicAdd(&g_ps[o0 + 8], ps1);
    }

    // column partials -> global (symmetric counterpart), off-diagonal only
    if (!diag) {
        __syncthreads();
        if (tid < 128) {
            size_t oc = (size_t)b * Nn + c0 + tid;
            atomicAdd(&g_te[oc], colte[tid]);
            float vse = colse[tid], vps = colps[tid];
            if (vse != 0.f) atomicAdd(&g_se[oc], vse);
            if (vps != 0.f) atomicAdd(&g_ps[oc], vps);
        }
    }
}

// ---------------- kernel 4: per-row log + per-instance fold ----------------
__global__ void row_kernel() {
    __shared__ float s_lp[Ii];
    __shared__ float s_ln[Ii];
    int t = threadIdx.x;
    int idx = blockIdx.x * 256 + t;
    int b = idx >> 12;
    if (t < Ii) { s_lp[t] = 0.f; s_ln[t] = 0.f; }
    __syncthreads();
    int i = g_insts[idx];
    if (i >= 0) {
        atomicAdd(&s_lp[i], g_ps[idx]);
        float neg = g_te[idx] - g_se[idx];
        atomicAdd(&s_ln[i], logf(fmaxf(neg, 1e-30f)));
    }
    __syncthreads();
    if (t < Ii) {
        if (s_lp[t] != 0.f) atomicAdd(&g_lp[b * Ii + t], s_lp[t]);
        if (s_ln[t] != 0.f) atomicAdd(&g_ln[b * Ii + t], s_ln[t]);
    }
}

// ---------------- kernel 5: tiny finish ----------------
__global__ void final_kernel(float* out) {
    __shared__ float s_red[128];
    int t = threadIdx.x;
    float cnt = (float)g_cnt[t];
    float valid = (cnt >= 5.0f) ? 1.0f : 0.0f;
    float lp = g_lp[t] / fmaxf(cnt * cnt, 1.0f);
    float ln = g_ln[t] / fmaxf(cnt, 1.0f);
    s_red[t] = valid * (WP * lp + (1.0f - WP) * ln);
    __syncthreads();
    for (int off = 64; off > 0; off >>= 1) {
        if (t < off) s_red[t] += s_red[t + off];
        __syncthreads();
    }
    if (t == 0) out[0] = s_red[0] / (float)(Bb * Ii);
}

// ---------------- launch ----------------
#define SIM_SMEM ((2 * 128 * STR + 384) * 4)

extern "C" void kernel_launch(void* const* d_in, const int* in_sizes, int n_in,
                              void* d_out, int out_size) {
    const float* x   = (const float*)d_in[0];
    const void*  lab = d_in[1];
    float* out = (float*)d_out;

    cudaFuncSetAttribute(sim_kernel, cudaFuncAttributeMaxDynamicSharedMemorySize, SIM_SMEM);

    detect_kernel<<<1, 256>>>((const unsigned int*)lab);
    inst_kernel<<<(Bb * Nn + 255) / 256, 256>>>(lab);
    ofs_kernel<<<1, 32>>>();
    pos_kernel<<<(Bb * Nn + 255) / 256, 256>>>();
    copy_kernel<<<(Bb * Nn * 16) / 256, 256>>>(x);
    sim_kernel<<<Bb * TPB, 256, SIM_SMEM>>>();
    row_kernel<<<Bb * Nn / 256, 256>>>();
    final_kernel<<<1, 128>>>(out);
}